// round 1
// baseline (speedup 1.0000x reference)
#include <cuda_runtime.h>
#include <cstdint>

// Constants from the reference (fp32).
#define C_EPS     1e-12f
#define C_TOL     1e-6f
#define C_LAM     10000.0f
#define C_INVLAM  1e-4f     // 1/LAM exactly representable enough (1e-4f)

// phi(t) = (p - t*A)*U - (b + t/LAM) * sqrt(max(N - 2tp + t^2 A, EPS)),  U=1
// Return phi(t) > 0 without computing sqrt:
//   L = p - t*A,  R = b + t/LAM,  nrm2 = max(N - 2tp + t^2 A, EPS) (= nrm^2 exactly)
//   R >= 0:  pos = (L > 0) && (L^2 >  R^2 * nrm2)
//   R <  0:  pos = (L >= 0) || (L^2 <  R^2 * nrm2)
__device__ __forceinline__ bool phi_pos(float t, float A, float p, float N, float b) {
    float nrm2 = fmaxf(fmaf(t, fmaf(t, A, -2.0f * p), N), C_EPS);
    float L    = fmaf(-t, A, p);
    float R    = fmaf(t, C_INVLAM, b);
    float L2   = L * L;
    float Rn2  = (R * R) * nrm2;
    if (R >= 0.0f) return (L > 0.0f) && (L2 > Rn2);
    return (L >= 0.0f) || (L2 < Rn2);
}

__global__ void __launch_bounds__(256) cbf_qp_kernel(
    const float* __restrict__ u_nom,   // [n, 2]
    const float* __restrict__ obs,     // [n, 6]
    float*       __restrict__ out,     // [n, 2]
    int n)
{
    int i = blockIdx.x * blockDim.x + threadIdx.x;
    if (i >= n) return;

    // Loads: all 8-byte aligned vector loads.
    float2 u  = *reinterpret_cast<const float2*>(u_nom + 2 * i);
    const float* o = obs + 6 * i;
    float2 pr = *reinterpret_cast<const float2*>(o + 2);  // p_rel
    float2 vh = *reinterpret_cast<const float2*>(o + 4);  // v_human

    float px = pr.x, py = pr.y;
    float h  = fmaf(px, px, py * py) - 1.0f;               // SAFE_DIST^2 = 1
    float ax = -2.0f * px, ay = -2.0f * py;
    float b  = fmaf(2.0f, h, -2.0f * fmaf(px, vh.x, py * vh.y));  // ALPHA*h - 2 p.v

    float A = fmaf(ax, ax, ay * ay);
    float p = fmaf(ax, u.x, ay * u.y);
    float N = fmaf(u.x, u.x, u.y * u.y);

    // Case 1: clip to unit ball, check feasibility.
    float nn  = sqrtf(fmaxf(N, C_EPS));
    float s1  = fminf(1.0f, 1.0f / nn);                    // U_MAX = 1
    float u1x = u.x * s1, u1y = u.y * s1;
    bool feas1 = fmaf(ax, u1x, ay * u1y) <= b + C_TOL;

    // Case 2: halfspace projection (soft), check ball.
    float t2  = (C_LAM * (p - b)) / fmaf(C_LAM, A, 1.0f);
    float u2x = fmaf(-t2, ax, u.x), u2y = fmaf(-t2, ay, u.y);
    bool ok2  = (t2 >= -C_TOL) && (fmaf(u2x, u2x, u2y * u2y) <= 1.0f + C_TOL);

    float ox, oy;
    if (feas1) {
        ox = u1x; oy = u1y;
    } else if (ok2) {
        ox = u2x; oy = u2y;
    } else {
        // Case 3: both constraints active. Bracket + bisect + Newton on phi.
        float th = 1.0f;
        #pragma unroll 4
        for (int k = 0; k < 40; k++)
            th = phi_pos(th, A, p, N, b) ? th * 2.0f : th;

        float lo = 0.0f, hi = th;
        #pragma unroll 4
        for (int k = 0; k < 60; k++) {
            float mid = 0.5f * (lo + hi);
            if (phi_pos(mid, A, p, N, b)) lo = mid; else hi = mid;
        }
        float t3 = 0.5f * (lo + hi);

        // 3 Newton polish steps (mirrors reference fp32 math, sqrt on MUFU).
        #pragma unroll
        for (int k = 0; k < 3; k++) {
            float nrm = sqrtf(fmaxf(fmaf(t3, fmaf(t3, A, -2.0f * p), N), C_EPS));
            float R   = fmaf(t3, C_INVLAM, b);
            float f   = fmaf(-t3, A, p) - R * nrm;
            float df  = -A - nrm * C_INVLAM - R * (fmaf(t3, A, -p)) / nrm;
            df = (fabsf(df) > 1e-8f) ? df : -1e-8f;
            t3 = t3 - f / df;
        }
        float nrm3 = sqrtf(fmaxf(fmaf(t3, fmaf(t3, A, -2.0f * p), N), C_EPS));
        float k3   = fmaxf(nrm3, 1.0f);
        float inv  = 1.0f / k3;
        ox = fmaf(-t3, ax, u.x) * inv;
        oy = fmaf(-t3, ay, u.y) * inv;
    }

    *reinterpret_cast<float2*>(out + 2 * i) = make_float2(ox, oy);
}

extern "C" void kernel_launch(void* const* d_in, const int* in_sizes, int n_in,
                              void* d_out, int out_size) {
    const float* u_nom = (const float*)d_in[0];   // [B,2] float32
    const float* obs   = (const float*)d_in[1];   // [B,6] float32
    float* out = (float*)d_out;                   // [B,2] float32

    int n = in_sizes[0] / 2;
    int threads = 256;
    int blocks  = (n + threads - 1) / threads;
    cbf_qp_kernel<<<blocks, threads>>>(u_nom, obs, out, n);
}

// round 2
// speedup vs baseline: 3.0669x; 3.0669x over previous
#include <cuda_runtime.h>
#include <cstdint>

#define C_EPS     1e-12f
#define C_TOL     1e-6f
#define C_LAM     10000.0f
#define C_INVLAM  1e-4f

#define MAX_B 4194304

// Compaction queue for case-3 rows (static device scratch — no allocation).
__device__ int g_count;
__device__ int g_idx[MAX_B];

// phi(t) > 0 without sqrt:
//   L = p - t*A, R = b + t/LAM, nrm2 = max(N - 2tp + t^2 A, EPS) = nrm^2 exactly
//   R >= 0: pos = (L > 0) && (L^2 >  R^2 * nrm2)
//   R <  0: pos = (L >= 0) || (L^2 <  R^2 * nrm2)
__device__ __forceinline__ bool phi_pos(float t, float A, float p, float N, float b) {
    float nrm2 = fmaxf(fmaf(t, fmaf(t, A, -2.0f * p), N), C_EPS);
    float L    = fmaf(-t, A, p);
    float R    = fmaf(t, C_INVLAM, b);
    float L2   = L * L;
    float Rn2  = (R * R) * nrm2;
    if (R >= 0.0f) return (L > 0.0f) && (L2 > Rn2);
    return (L >= 0.0f) || (L2 < Rn2);
}

__device__ __forceinline__ void load_row(
    const float* __restrict__ u_nom, const float* __restrict__ obs, int i,
    float& ux, float& uy, float& ax, float& ay, float& A, float& p, float& N, float& b)
{
    float2 u  = *reinterpret_cast<const float2*>(u_nom + 2 * i);
    const float* o = obs + 6 * i;
    float2 pr = *reinterpret_cast<const float2*>(o + 2);
    float2 vh = *reinterpret_cast<const float2*>(o + 4);
    float px = pr.x, py = pr.y;
    float h  = fmaf(px, px, py * py) - 1.0f;
    ax = -2.0f * px; ay = -2.0f * py;
    b  = fmaf(2.0f, h, -2.0f * fmaf(px, vh.x, py * vh.y));
    A  = fmaf(ax, ax, ay * ay);
    p  = fmaf(ax, u.x, ay * u.y);
    N  = fmaf(u.x, u.x, u.y * u.y);
    ux = u.x; uy = u.y;
}

__global__ void reset_kernel() { g_count = 0; }

// Pass 1: solve cases 1 & 2, compact case-3 indices.
__global__ void __launch_bounds__(256) pass1_kernel(
    const float* __restrict__ u_nom,
    const float* __restrict__ obs,
    float*       __restrict__ out,
    int n)
{
    int i = blockIdx.x * 256 + threadIdx.x;
    bool valid = i < n;
    bool need3 = false;

    if (valid) {
        float ux, uy, ax, ay, A, p, N, b;
        load_row(u_nom, obs, i, ux, uy, ax, ay, A, p, N, b);

        // Case 1
        float nn  = sqrtf(fmaxf(N, C_EPS));
        float s1  = fminf(1.0f, 1.0f / nn);
        float u1x = ux * s1, u1y = uy * s1;
        bool feas1 = fmaf(ax, u1x, ay * u1y) <= b + C_TOL;

        // Case 2
        float t2  = (C_LAM * (p - b)) / fmaf(C_LAM, A, 1.0f);
        float u2x = fmaf(-t2, ax, ux), u2y = fmaf(-t2, ay, uy);
        bool ok2  = (t2 >= -C_TOL) && (fmaf(u2x, u2x, u2y * u2y) <= 1.0f + C_TOL);

        if (feas1) {
            *reinterpret_cast<float2*>(out + 2 * i) = make_float2(u1x, u1y);
        } else if (ok2) {
            *reinterpret_cast<float2*>(out + 2 * i) = make_float2(u2x, u2y);
        } else {
            need3 = true;
        }
    }

    // Block-aggregated compaction (one global atomic per block).
    unsigned mask = __ballot_sync(0xffffffffu, need3);
    int lane = threadIdx.x & 31;
    int wrp  = threadIdx.x >> 5;
    __shared__ int warp_off[8];
    __shared__ int base_s;
    if (lane == 0) warp_off[wrp] = __popc(mask);
    __syncthreads();
    if (threadIdx.x == 0) {
        int tot = 0;
        #pragma unroll
        for (int w = 0; w < 8; w++) { int c = warp_off[w]; warp_off[w] = tot; tot += c; }
        base_s = tot ? atomicAdd(&g_count, tot) : 0;
    }
    __syncthreads();
    if (need3) {
        int pos = base_s + warp_off[wrp] + __popc(mask & ((1u << lane) - 1u));
        g_idx[pos] = i;
    }
}

// Pass 2: case-3 rootfind on compacted rows (full warps).
__global__ void __launch_bounds__(256) pass2_kernel(
    const float* __restrict__ u_nom,
    const float* __restrict__ obs,
    float*       __restrict__ out)
{
    const int total  = g_count;
    const int stride = gridDim.x * blockDim.x;

    for (int base = blockIdx.x * blockDim.x + threadIdx.x; ; base += stride) {
        bool valid = base < total;
        if (!__any_sync(0xffffffffu, valid)) break;

        int i = valid ? g_idx[base] : g_idx[0];

        float ux, uy, ax, ay, A, p, N, b;
        load_row(u_nom, obs, i, ux, uy, ax, ay, A, p, N, b);

        // Doubling bracket, warp-early-exit. Matches reference semantics:
        // th latches once phi(th) <= 0 (recomputation gives same predicate).
        float th = 1.0f;
        #pragma unroll 1
        for (int k = 0; k < 40; k++) {
            bool pos = valid && phi_pos(th, A, p, N, b);
            th = pos ? th * 2.0f : th;
            if (!__any_sync(0xffffffffu, pos)) break;
        }

        // 16 bisections: root known to lie in [th/2, th] (or [0,1] if th==1),
        // so this gives ~2^-17 relative bracket before Newton.
        float lo = 0.0f, hi = th;
        #pragma unroll
        for (int k = 0; k < 16; k++) {
            float mid = 0.5f * (lo + hi);
            bool pos = phi_pos(mid, A, p, N, b);
            lo = pos ? mid : lo;
            hi = pos ? hi : mid;
        }
        float t3 = 0.5f * (lo + hi);

        // 4 Newton polish steps (ref does 3 from an exact bracket; Newton is
        // stationary at the root so the extra step only helps convergence).
        #pragma unroll
        for (int k = 0; k < 4; k++) {
            float nrm = sqrtf(fmaxf(fmaf(t3, fmaf(t3, A, -2.0f * p), N), C_EPS));
            float R   = fmaf(t3, C_INVLAM, b);
            float f   = fmaf(-t3, A, p) - R * nrm;
            float df  = -A - nrm * C_INVLAM - R * (fmaf(t3, A, -p)) / nrm;
            df = (fabsf(df) > 1e-8f) ? df : -1e-8f;
            t3 = t3 - f / df;
        }

        float nrm3 = sqrtf(fmaxf(fmaf(t3, fmaf(t3, A, -2.0f * p), N), C_EPS));
        float inv  = 1.0f / fmaxf(nrm3, 1.0f);
        float ox   = fmaf(-t3, ax, ux) * inv;
        float oy   = fmaf(-t3, ay, uy) * inv;

        if (valid)
            *reinterpret_cast<float2*>(out + 2 * i) = make_float2(ox, oy);
    }
}

extern "C" void kernel_launch(void* const* d_in, const int* in_sizes, int n_in,
                              void* d_out, int out_size) {
    const float* u_nom = (const float*)d_in[0];
    const float* obs   = (const float*)d_in[1];
    float* out = (float*)d_out;

    int n = in_sizes[0] / 2;
    int threads = 256;
    int blocks  = (n + threads - 1) / threads;

    reset_kernel<<<1, 1>>>();
    pass1_kernel<<<blocks, threads>>>(u_nom, obs, out, n);
    pass2_kernel<<<2048, threads>>>(u_nom, obs, out);
}

// round 3
// speedup vs baseline: 3.1535x; 1.0282x over previous
#include <cuda_runtime.h>
#include <cstdint>

#define C_EPS     1e-12f
#define C_TOL     1e-6f
#define C_LAM     10000.0f
#define C_INVLAM  1e-4f

#define MAX_B 4194304

// Compaction scratch (static device memory — no allocation).
__device__ int    g_count = 0;
__device__ int    g_done  = 0;
__device__ float4 g_pay4[MAX_B];   // ux, uy, ax, ay
__device__ float2 g_pay2[MAX_B];   // b, bitcast(row index)

// phi(t) > 0 without sqrt:
//   L = p - t*A, R = b + t/LAM, nrm2 = max(N - 2tp + t^2 A, EPS) = nrm^2 exactly
//   R >= 0: pos = (L > 0) && (L^2 >  R^2 * nrm2)
//   R <  0: pos = (L >= 0) || (L^2 <  R^2 * nrm2)
__device__ __forceinline__ bool phi_pos(float t, float A, float p, float N, float b) {
    float nrm2 = fmaxf(fmaf(t, fmaf(t, A, -2.0f * p), N), C_EPS);
    float L    = fmaf(-t, A, p);
    float R    = fmaf(t, C_INVLAM, b);
    float L2   = L * L;
    float Rn2  = (R * R) * nrm2;
    if (R >= 0.0f) return (L > 0.0f) && (L2 > Rn2);
    return (L >= 0.0f) || (L2 < Rn2);
}

// Pass 1: solve cases 1 & 2, compact case-3 payloads (coalesced SoA).
__global__ void __launch_bounds__(256) pass1_kernel(
    const float* __restrict__ u_nom,
    const float* __restrict__ obs,
    float*       __restrict__ out,
    int n)
{
    int i = blockIdx.x * 256 + threadIdx.x;
    bool valid = i < n;
    bool need3 = false;
    float ux = 0.f, uy = 0.f, ax = 0.f, ay = 0.f, b = 0.f;

    if (valid) {
        float2 u  = *reinterpret_cast<const float2*>(u_nom + 2 * i);
        const float* o = obs + 6 * i;
        float2 pr = *reinterpret_cast<const float2*>(o + 2);
        float2 vh = *reinterpret_cast<const float2*>(o + 4);
        float px = pr.x, py = pr.y;
        float h  = fmaf(px, px, py * py) - 1.0f;
        ax = -2.0f * px; ay = -2.0f * py;
        b  = fmaf(2.0f, h, -2.0f * fmaf(px, vh.x, py * vh.y));
        ux = u.x; uy = u.y;

        float A = fmaf(ax, ax, ay * ay);
        float p = fmaf(ax, ux, ay * uy);
        float N = fmaf(ux, ux, uy * uy);

        // Case 1
        float nn  = sqrtf(fmaxf(N, C_EPS));
        float s1  = fminf(1.0f, 1.0f / nn);
        float u1x = ux * s1, u1y = uy * s1;
        bool feas1 = fmaf(ax, u1x, ay * u1y) <= b + C_TOL;

        // Case 2
        float t2  = (C_LAM * (p - b)) / fmaf(C_LAM, A, 1.0f);
        float u2x = fmaf(-t2, ax, ux), u2y = fmaf(-t2, ay, uy);
        bool ok2  = (t2 >= -C_TOL) && (fmaf(u2x, u2x, u2y * u2y) <= 1.0f + C_TOL);

        if (feas1) {
            *reinterpret_cast<float2*>(out + 2 * i) = make_float2(u1x, u1y);
        } else if (ok2) {
            *reinterpret_cast<float2*>(out + 2 * i) = make_float2(u2x, u2y);
        } else {
            need3 = true;
        }
    }

    // Block-aggregated compaction (one global atomic per block).
    unsigned mask = __ballot_sync(0xffffffffu, need3);
    int lane = threadIdx.x & 31;
    int wrp  = threadIdx.x >> 5;
    __shared__ int warp_off[8];
    __shared__ int base_s;
    if (lane == 0) warp_off[wrp] = __popc(mask);
    __syncthreads();
    if (threadIdx.x == 0) {
        int tot = 0;
        #pragma unroll
        for (int w = 0; w < 8; w++) { int c = warp_off[w]; warp_off[w] = tot; tot += c; }
        base_s = tot ? atomicAdd(&g_count, tot) : 0;
    }
    __syncthreads();
    if (need3) {
        int pos = base_s + warp_off[wrp] + __popc(mask & ((1u << lane) - 1u));
        g_pay4[pos] = make_float4(ux, uy, ax, ay);
        g_pay2[pos] = make_float2(b, __int_as_float(i));
    }
}

// Pass 2: case-3 rootfind on compacted payloads (coalesced reads, full warps).
// Last block to finish resets the counters for the next graph replay.
__global__ void __launch_bounds__(256) pass2_kernel(float* __restrict__ out)
{
    const int total  = g_count;
    const int stride = gridDim.x * blockDim.x;

    for (int base = blockIdx.x * blockDim.x + threadIdx.x; ; base += stride) {
        bool valid = base < total;
        if (!__any_sync(0xffffffffu, valid)) break;

        int idx = valid ? base : 0;
        float4 p4 = g_pay4[idx];
        float2 p2 = g_pay2[idx];
        float ux = p4.x, uy = p4.y, ax = p4.z, ay = p4.w;
        float b  = p2.x;
        int   i  = __float_as_int(p2.y);

        float A = fmaf(ax, ax, ay * ay);
        float p = fmaf(ax, ux, ay * uy);
        float N = fmaf(ux, ux, uy * uy);

        // Doubling bracket, warp-early-exit (th latches once phi(th) <= 0).
        float th = 1.0f;
        #pragma unroll 1
        for (int k = 0; k < 40; k++) {
            bool pos = valid && phi_pos(th, A, p, N, b);
            th = pos ? th * 2.0f : th;
            if (!__any_sync(0xffffffffu, pos)) break;
        }

        // 12 bisections -> relative bracket ~2^-13, then Newton polishes.
        float lo = 0.0f, hi = th;
        #pragma unroll
        for (int k = 0; k < 12; k++) {
            float mid = 0.5f * (lo + hi);
            bool pos = phi_pos(mid, A, p, N, b);
            lo = pos ? mid : lo;
            hi = pos ? hi : mid;
        }
        float t3 = 0.5f * (lo + hi);

        // 4 Newton steps (quadratic: 2e-4 -> fp32 precision).
        #pragma unroll
        for (int k = 0; k < 4; k++) {
            float nrm = sqrtf(fmaxf(fmaf(t3, fmaf(t3, A, -2.0f * p), N), C_EPS));
            float R   = fmaf(t3, C_INVLAM, b);
            float f   = fmaf(-t3, A, p) - R * nrm;
            float df  = -A - nrm * C_INVLAM - R * (fmaf(t3, A, -p)) / nrm;
            df = (fabsf(df) > 1e-8f) ? df : -1e-8f;
            t3 = t3 - f / df;
        }

        float nrm3 = sqrtf(fmaxf(fmaf(t3, fmaf(t3, A, -2.0f * p), N), C_EPS));
        float inv  = 1.0f / fmaxf(nrm3, 1.0f);
        float ox   = fmaf(-t3, ax, ux) * inv;
        float oy   = fmaf(-t3, ay, uy) * inv;

        if (valid)
            *reinterpret_cast<float2*>(out + 2 * i) = make_float2(ox, oy);
    }

    // Reset counters for the next replay: last block to arrive does it.
    __syncthreads();
    if (threadIdx.x == 0) {
        __threadfence();
        int d = atomicAdd(&g_done, 1);
        if (d == (int)gridDim.x - 1) {
            g_count = 0;
            g_done  = 0;
            __threadfence();
        }
    }
}

extern "C" void kernel_launch(void* const* d_in, const int* in_sizes, int n_in,
                              void* d_out, int out_size) {
    const float* u_nom = (const float*)d_in[0];
    const float* obs   = (const float*)d_in[1];
    float* out = (float*)d_out;

    int n = in_sizes[0] / 2;
    int threads = 256;
    int blocks  = (n + threads - 1) / threads;

    pass1_kernel<<<blocks, threads>>>(u_nom, obs, out, n);
    pass2_kernel<<<2048, threads>>>(out);
}

// round 4
// speedup vs baseline: 4.3748x; 1.3873x over previous
#include <cuda_runtime.h>
#include <cstdint>

#define C_EPS     1e-12f
#define C_TOL     1e-6f
#define C_LAM     10000.0f
#define C_INVLAM  1e-4f

// Fully fused CBF-QP projection.
// Case 1: clip to unit ball if feasible.
// Case 2: soft halfspace projection if inside ball.
// Case 3: both constraints active -> root of
//   phi(t) = (p - tA) - (b + t/LAM)*||u - t a|| = 0
// Analytic start (quadratic from dropping t/LAM, or deep-infeasible asymptote),
// then 4 clamped Newton steps. Same unique root the reference's
// doubling+bisection+Newton converges to.
__global__ void __launch_bounds__(256) cbf_fused_kernel(
    const float* __restrict__ u_nom,   // [n,2]
    const float* __restrict__ obs,     // [n,6]
    float*       __restrict__ out,     // [n,2]
    int n)
{
    int i = blockIdx.x * 256 + threadIdx.x;
    if (i >= n) return;

    float2 u  = *reinterpret_cast<const float2*>(u_nom + 2 * i);
    const float* o = obs + 6 * i;
    float2 pr = *reinterpret_cast<const float2*>(o + 2);
    float2 vh = *reinterpret_cast<const float2*>(o + 4);

    float px = pr.x, py = pr.y;
    float h  = fmaf(px, px, py * py) - 1.0f;                      // SAFE_DIST^2 = 1
    float ax = -2.0f * px, ay = -2.0f * py;
    float b  = fmaf(2.0f, h, -2.0f * fmaf(px, vh.x, py * vh.y)); // ALPHA*h - 2 p.v

    float A = fmaf(ax, ax, ay * ay);
    float p = fmaf(ax, u.x, ay * u.y);
    float N = fmaf(u.x, u.x, u.y * u.y);

    // ---- Case 1: clip to unit ball, test feasibility ----
    float s1  = fminf(1.0f, rsqrtf(fmaxf(N, C_EPS)));   // min(1, U/||u||)
    float u1x = u.x * s1, u1y = u.y * s1;
    bool feas1 = fmaf(ax, u1x, ay * u1y) <= b + C_TOL;

    // ---- Case 2: soft halfspace projection, test ball ----
    float t2  = __fdividef(C_LAM * (p - b), fmaf(C_LAM, A, 1.0f));
    float u2x = fmaf(-t2, ax, u.x), u2y = fmaf(-t2, ay, u.y);
    bool ok2  = (t2 >= -C_TOL) && (fmaf(u2x, u2x, u2y * u2y) <= 1.0f + C_TOL);

    float ox = feas1 ? u1x : u2x;
    float oy = feas1 ? u1y : u2y;
    bool need3 = !(feas1 || ok2);

    // ---- Case 3 (predicated; skipped only if no lane needs it) ----
    if (__any_sync(__activemask(), need3)) {
        float Ac   = fmaxf(A, 1e-30f);
        float rsA  = rsqrtf(Ac);
        float sa   = Ac * rsA;                 // sqrt(A)
        float invA = rsA * rsA;                // 1/A

        // Quadratic start (valid when A - b^2 > 0):
        //   t_q = ( p - b*sqrt((A*N - p^2)/(A - b^2)) ) / A
        float s    = A - b * b;
        float cs2  = fmaxf(fmaf(A, N, -p * p), 0.0f);   // A*N - p^2 >= 0
        float rad  = sqrtf(fmaxf(__fdividef(cs2, s), 0.0f));
        float t_q  = fmaf(-b, rad, p) * invA;

        // Deep-infeasible start (b < 0, b^2 >= A): t ~ LAM*(-b - sqrt(A))
        float t_dp = C_LAM * (-b - sa);

        float t3 = (s > 0.0f) ? t_q : t_dp;

        // Provable upper bound on the root (keeps Newton safeguarded):
        //   b >= 0: root <= p/A ;  b < 0: root <= max(p/A, -LAM*b)
        float hb = p * invA;
        if (b < 0.0f) hb = fmaxf(hb, -C_LAM * b);
        t3 = fminf(fmaxf(t3, 0.0f), hb);

        // 4 clamped Newton steps on the exact phi.
        #pragma unroll
        for (int k = 0; k < 4; k++) {
            float nrm2 = fmaxf(fmaf(t3, fmaf(t3, A, -2.0f * p), N), C_EPS);
            float rnrm = rsqrtf(nrm2);
            float nrm  = nrm2 * rnrm;
            float R    = fmaf(t3, C_INVLAM, b);
            float L    = fmaf(-t3, A, p);
            float f    = fmaf(-R, nrm, L);
            // df = -A - nrm/LAM - R*(tA - p)/nrm ;  (tA - p) = -L
            float df   = fmaf(R * L, rnrm, fmaf(-C_INVLAM, nrm, -A));
            df = (fabsf(df) > 1e-8f) ? df : -1e-8f;
            t3 = t3 - __fdividef(f, df);
            t3 = fminf(fmaxf(t3, 0.0f), hb);
        }

        float nrm2 = fmaxf(fmaf(t3, fmaf(t3, A, -2.0f * p), N), C_EPS);
        float inv  = fminf(rsqrtf(nrm2), 1.0f);          // 1/max(||u-ta||,1)
        float u3x  = fmaf(-t3, ax, u.x) * inv;
        float u3y  = fmaf(-t3, ay, u.y) * inv;

        ox = need3 ? u3x : ox;
        oy = need3 ? u3y : oy;
    }

    *reinterpret_cast<float2*>(out + 2 * i) = make_float2(ox, oy);
}

extern "C" void kernel_launch(void* const* d_in, const int* in_sizes, int n_in,
                              void* d_out, int out_size) {
    const float* u_nom = (const float*)d_in[0];
    const float* obs   = (const float*)d_in[1];
    float* out = (float*)d_out;

    int n = in_sizes[0] / 2;
    int threads = 256;
    int blocks  = (n + threads - 1) / threads;
    cbf_fused_kernel<<<blocks, threads>>>(u_nom, obs, out, n);
}

// round 5
// speedup vs baseline: 6.2583x; 1.4305x over previous
#include <cuda_runtime.h>
#include <cstdint>

#define C_EPS     1e-12f
#define C_TOL     1e-6f
#define C_LAM     10000.0f
#define C_INVLAM  1e-4f

// Fully fused CBF-QP projection.
// Case 1: clip to unit ball if feasible.
// Case 2: soft halfspace projection if inside ball.
// Case 3: both constraints active -> root of
//   phi(t) = (p - tA) - (b + t/LAM)*||u - t a|| = 0
// Analytic start (quadratic from dropping t/LAM, or deep-infeasible asymptote),
// then 4 clamped Newton steps. Same unique root the reference's
// doubling+bisection+Newton converges to.
__global__ void __launch_bounds__(256) cbf_fused_kernel(
    const float* __restrict__ u_nom,   // [n,2]
    const float* __restrict__ obs,     // [n,6]
    float*       __restrict__ out,     // [n,2]
    int n)
{
    int i = blockIdx.x * 256 + threadIdx.x;
    if (i >= n) return;

    float2 u  = *reinterpret_cast<const float2*>(u_nom + 2 * i);
    const float* o = obs + 6 * i;
    float2 pr = *reinterpret_cast<const float2*>(o + 2);
    float2 vh = *reinterpret_cast<const float2*>(o + 4);

    float px = pr.x, py = pr.y;
    float h  = fmaf(px, px, py * py) - 1.0f;                      // SAFE_DIST^2 = 1
    float ax = -2.0f * px, ay = -2.0f * py;
    float b  = fmaf(2.0f, h, -2.0f * fmaf(px, vh.x, py * vh.y)); // ALPHA*h - 2 p.v

    float A = fmaf(ax, ax, ay * ay);
    float p = fmaf(ax, u.x, ay * u.y);
    float N = fmaf(u.x, u.x, u.y * u.y);

    // ---- Case 1: clip to unit ball, test feasibility ----
    float s1  = fminf(1.0f, rsqrtf(fmaxf(N, C_EPS)));   // min(1, U/||u||)
    float u1x = u.x * s1, u1y = u.y * s1;
    bool feas1 = fmaf(ax, u1x, ay * u1y) <= b + C_TOL;

    // ---- Case 2: soft halfspace projection, test ball ----
    float t2  = __fdividef(C_LAM * (p - b), fmaf(C_LAM, A, 1.0f));
    float u2x = fmaf(-t2, ax, u.x), u2y = fmaf(-t2, ay, u.y);
    bool ok2  = (t2 >= -C_TOL) && (fmaf(u2x, u2x, u2y * u2y) <= 1.0f + C_TOL);

    float ox = feas1 ? u1x : u2x;
    float oy = feas1 ? u1y : u2y;
    bool need3 = !(feas1 || ok2);

    // ---- Case 3 (predicated; skipped only if no lane needs it) ----
    if (__any_sync(__activemask(), need3)) {
        float Ac   = fmaxf(A, 1e-30f);
        float rsA  = rsqrtf(Ac);
        float sa   = Ac * rsA;                 // sqrt(A)
        float invA = rsA * rsA;                // 1/A

        // Quadratic start (valid when A - b^2 > 0):
        //   t_q = ( p - b*sqrt((A*N - p^2)/(A - b^2)) ) / A
        float s    = A - b * b;
        float cs2  = fmaxf(fmaf(A, N, -p * p), 0.0f);   // A*N - p^2 >= 0
        float rad  = sqrtf(fmaxf(__fdividef(cs2, s), 0.0f));
        float t_q  = fmaf(-b, rad, p) * invA;

        // Deep-infeasible start (b < 0, b^2 >= A): t ~ LAM*(-b - sqrt(A))
        float t_dp = C_LAM * (-b - sa);

        float t3 = (s > 0.0f) ? t_q : t_dp;

        // Provable upper bound on the root (keeps Newton safeguarded):
        //   b >= 0: root <= p/A ;  b < 0: root <= max(p/A, -LAM*b)
        float hb = p * invA;
        if (b < 0.0f) hb = fmaxf(hb, -C_LAM * b);
        t3 = fminf(fmaxf(t3, 0.0f), hb);

        // 4 clamped Newton steps on the exact phi.
        #pragma unroll
        for (int k = 0; k < 4; k++) {
            float nrm2 = fmaxf(fmaf(t3, fmaf(t3, A, -2.0f * p), N), C_EPS);
            float rnrm = rsqrtf(nrm2);
            float nrm  = nrm2 * rnrm;
            float R    = fmaf(t3, C_INVLAM, b);
            float L    = fmaf(-t3, A, p);
            float f    = fmaf(-R, nrm, L);
            // df = -A - nrm/LAM - R*(tA - p)/nrm ;  (tA - p) = -L
            float df   = fmaf(R * L, rnrm, fmaf(-C_INVLAM, nrm, -A));
            df = (fabsf(df) > 1e-8f) ? df : -1e-8f;
            t3 = t3 - __fdividef(f, df);
            t3 = fminf(fmaxf(t3, 0.0f), hb);
        }

        float nrm2 = fmaxf(fmaf(t3, fmaf(t3, A, -2.0f * p), N), C_EPS);
        float inv  = fminf(rsqrtf(nrm2), 1.0f);          // 1/max(||u-ta||,1)
        float u3x  = fmaf(-t3, ax, u.x) * inv;
        float u3y  = fmaf(-t3, ay, u.y) * inv;

        ox = need3 ? u3x : ox;
        oy = need3 ? u3y : oy;
    }

    *reinterpret_cast<float2*>(out + 2 * i) = make_float2(ox, oy);
}

extern "C" void kernel_launch(void* const* d_in, const int* in_sizes, int n_in,
                              void* d_out, int out_size) {
    const float* u_nom = (const float*)d_in[0];
    const float* obs   = (const float*)d_in[1];
    float* out = (float*)d_out;

    int n = in_sizes[0] / 2;
    int threads = 256;
    int blocks  = (n + threads - 1) / threads;
    cbf_fused_kernel<<<blocks, threads>>>(u_nom, obs, out, n);
}